// round 7
// baseline (speedup 1.0000x reference)
#include <cuda_runtime.h>
#include <cuda_bf16.h>
#include <cstdint>

#define FD 128
#define F4 32

static const int cNSOC = 100000;
static const int cNI2U = 50000;
static const int cESOC = 1600000;
static const int cEI2U = 800000;

// ---------------- scratch ----------------------------------------------------
__device__ __align__(16) float g_el1[cNI2U * FD];
__device__ __align__(16) float g_er1[cNI2U * FD];
__device__ __align__(16) float g_el2[cNSOC * FD];
__device__ __align__(16) float g_er2[cNSOC * FD];
__device__ __align__(16) float g_h1 [cNI2U * FD];
__device__ __align__(16) __nv_bfloat16 g_wbh[4][FD * FD];  // bf16 hi, transposed [n][k]
__device__ __align__(16) __nv_bfloat16 g_wbl[4][FD * FD];  // bf16 lo, transposed
__device__ int   g_map [cNSOC];
__device__ int   g_cnt1[cNI2U];
__device__ int   g_cnt2[cNSOC];
__device__ int   g_off1[cNI2U + 1];
__device__ int   g_off2[cNSOC + 1];
__device__ int   g_csr1[cEI2U];
__device__ int   g_csr2[cESOC];
__device__ int   g_csum1[64];
__device__ int   g_csum2[128];

__device__ __forceinline__ float lrelu(float x, float s) { return x > 0.f ? x : s * x; }

__device__ __forceinline__ void bf16split2(float x, float y, unsigned& hi, unsigned& lo) {
    __nv_bfloat162 h = __floats2bfloat162_rn(x, y);
    float rx = x - __bfloat162float(__low2bfloat16(h));
    float ry = y - __bfloat162float(__high2bfloat16(h));
    __nv_bfloat162 l = __floats2bfloat162_rn(rx, ry);
    hi = *(unsigned*)&h;
    lo = *(unsigned*)&l;
}

__device__ __forceinline__ float4 ldg4_na(const float4* p) {
    float4 v;
    asm volatile("ld.global.nc.L1::no_allocate.v4.f32 {%0,%1,%2,%3}, [%4];"
                 : "=f"(v.x), "=f"(v.y), "=f"(v.z), "=f"(v.w) : "l"(p));
    return v;
}

// ---------------- init ---------------------------------------------------------
__global__ void k_init1() {
    int i = blockIdx.x * blockDim.x + threadIdx.x;
    if (i < cNSOC) g_map[i] = -1;
    if (i < cNI2U) g_cnt1[i] = 0;
    if (i == 0) g_off1[0] = 0;
}
__global__ void k_init2() {
    int i = blockIdx.x * blockDim.x + threadIdx.x;
    if (i < cNSOC) g_cnt2[i] = 0;
    if (i == 0) g_off2[0] = 0;
}

// ---------------- W split: fp32 [k][n] -> bf16 hi/lo transposed [n][k] ---------
__global__ void k_wsplit(const float* __restrict__ W0, const float* __restrict__ W1,
                         const float* __restrict__ W2, const float* __restrict__ W3) {
    int i = blockIdx.x * blockDim.x + threadIdx.x;
    int m = i >> 14, idx = i & 16383;
    int n = idx >> 7, k = idx & 127;
    const float* W = (m == 0) ? W0 : (m == 1) ? W1 : (m == 2) ? W2 : W3;
    float v = __ldg(W + k * FD + n);
    __nv_bfloat16 h = __float2bfloat16_rn(v);
    g_wbh[m][n * FD + k] = h;
    g_wbl[m][n * FD + k] = __float2bfloat16_rn(v - __bfloat162float(h));
}

// ---------------- CSR build ------------------------------------------------------
__global__ void k_hist(const int* __restrict__ dst, int* __restrict__ cnt, int E) {
    int e = blockIdx.x * blockDim.x + threadIdx.x;
    if (e < E) atomicAdd(cnt + __ldg(dst + e), 1);
}

__global__ void k_scanA(const int* __restrict__ cnt, int* __restrict__ off,
                        int* __restrict__ csum, int N) {
    __shared__ int sh[1024];
    int t = threadIdx.x;
    int i = blockIdx.x * 1024 + t;
    sh[t] = (i < N) ? cnt[i] : 0;
    __syncthreads();
#pragma unroll
    for (int d = 1; d < 1024; d <<= 1) {
        int add = (t >= d) ? sh[t - d] : 0;
        __syncthreads();
        sh[t] += add;
        __syncthreads();
    }
    if (i < N) off[i + 1] = sh[t];
    if (t == 1023) csum[blockIdx.x] = sh[t];
}

__global__ void k_scanB(int* __restrict__ c, int n) {
    __shared__ int sh[128];
    int t = threadIdx.x;
    sh[t] = (t < n) ? c[t] : 0;
    __syncthreads();
#pragma unroll
    for (int d = 1; d < 128; d <<= 1) {
        int add = (t >= d) ? sh[t - d] : 0;
        __syncthreads();
        sh[t] += add;
        __syncthreads();
    }
    if (t < n) c[t] = sh[t];
}

__global__ void k_scanC(int* __restrict__ off, const int* __restrict__ csum,
                        int* __restrict__ cur, int N) {
    int i = blockIdx.x * blockDim.x + threadIdx.x;
    if (i >= N) return;
    int ch = i >> 10;
    int c = cur[i];
    int inc = off[i + 1] + (ch > 0 ? csum[ch - 1] : 0);
    off[i + 1] = inc;
    cur[i] = inc - c;
}

__global__ void k_scatter(const int* __restrict__ src, const int* __restrict__ dst,
                          int* __restrict__ cur, int* __restrict__ csr, int E) {
    int e = blockIdx.x * blockDim.x + threadIdx.x;
    if (e >= E) return;
    int pos = atomicAdd(cur + __ldg(dst + e), 1);
    csr[pos] = __ldg(src + e);
}

// ---------------- tensor-core dual GEMM (bf16x3 split) ---------------------------
// LAYER 1: feat = emb[nid[g]],            out rows g        -> el1/er1
// LAYER 2: feat = emb[g],                 out rows g        -> el2/er2
// LAYER 3: feat = h1[g],  masked store to out rows nid[g]   -> el2/er2 (fix pass)
#define PA 66
#define PB 20
#define GEMM_SMEM ((2 * 128 * PA + 4 * 128 * PB) * 4)

#define MMA_BF16(ACC, A, B0, B1)                                                \
    asm volatile("mma.sync.aligned.m16n8k16.row.col.f32.bf16.bf16.f32 "         \
                 "{%0,%1,%2,%3}, {%4,%5,%6,%7}, {%8,%9}, {%0,%1,%2,%3};"        \
                 : "+f"(ACC[0]), "+f"(ACC[1]), "+f"(ACC[2]), "+f"(ACC[3])       \
                 : "r"(A[0]), "r"(A[1]), "r"(A[2]), "r"(A[3]), "r"(B0), "r"(B1))

template<int LAYER>
__global__ void __launch_bounds__(512, 1)
k_gemm_mma(const float* __restrict__ emb, const int* __restrict__ nid,
           const float* __restrict__ bs, const float* __restrict__ bd, int nrows)
{
    extern __shared__ unsigned smu[];
    unsigned* sf0 = smu;
    unsigned* sf1 = sf0 + 128 * PA;
    unsigned* sw  = sf1 + 128 * PA;

    const int mS = (LAYER == 1) ? 0 : 2;
    const int mD = (LAYER == 1) ? 1 : 3;
    float* outS = (LAYER == 1) ? g_el1 : g_el2;
    float* outD = (LAYER == 1) ? g_er1 : g_er2;

    const int tid = threadIdx.x;
    const int rowbase = blockIdx.x * 128;

    for (int s = tid; s < 128 * F4; s += 512) {
        int r = s >> 5, c4 = s & 31;
        int g = rowbase + r;
        float4 v = make_float4(0.f, 0.f, 0.f, 0.f);
        if (g < nrows) {
            const float* p;
            if (LAYER == 1)      p = emb + (size_t)__ldg(nid + g) * FD;
            else if (LAYER == 2) p = emb + (size_t)g * FD;
            else                 p = g_h1 + (size_t)g * FD;
            v = ((const float4*)p)[c4];
        }
        unsigned h0, l0, h1v, l1;
        bf16split2(v.x, v.y, h0, l0);
        bf16split2(v.z, v.w, h1v, l1);
        int w = r * PA + c4 * 2;
        sf0[w] = h0; sf0[w + 1] = h1v;
        sf1[w] = l0; sf1[w + 1] = l1;
    }

    const int lane = tid & 31, warp = tid >> 5;
    const int mtile = warp >> 1, half = warp & 1;
    const int gid = lane >> 2, tig = lane & 3;

    unsigned* swh = sw + (half * 2 + 0) * 128 * PB;
    unsigned* swl = sw + (half * 2 + 1) * 128 * PB;

    float acc[16][4];
#pragma unroll
    for (int j = 0; j < 16; j++)
#pragma unroll
        for (int q = 0; q < 4; q++) acc[j][q] = 0.f;

    const __nv_bfloat16* wbhS = g_wbh[mS];
    const __nv_bfloat16* wblS = g_wbl[mS];
    const __nv_bfloat16* wbhD = g_wbh[mD];
    const __nv_bfloat16* wblD = g_wbl[mD];

    for (int ch = 0; ch < 4; ch++) {
        __syncthreads();
        {
            int n = tid >> 2, q = tid & 3;
            int gsrc = (n * FD + ch * 32) / 8 + q;
            int wdst = n * PB + q * 4;
            ((uint4*)(sw + 0 * 128 * PB + wdst))[0] = ((const uint4*)wbhS)[gsrc];
            ((uint4*)(sw + 1 * 128 * PB + wdst))[0] = ((const uint4*)wblS)[gsrc];
            ((uint4*)(sw + 2 * 128 * PB + wdst))[0] = ((const uint4*)wbhD)[gsrc];
            ((uint4*)(sw + 3 * 128 * PB + wdst))[0] = ((const uint4*)wblD)[gsrc];
        }
        __syncthreads();

#pragma unroll
        for (int kk = 0; kk < 2; kk++) {
            int kb = ch * 16 + kk * 8;
            int row0 = mtile * 16 + gid;
            unsigned A0[4], A1[4];
            A0[0] = sf0[ row0      * PA + kb + tig];
            A0[1] = sf0[(row0 + 8) * PA + kb + tig];
            A0[2] = sf0[ row0      * PA + kb + tig + 4];
            A0[3] = sf0[(row0 + 8) * PA + kb + tig + 4];
            A1[0] = sf1[ row0      * PA + kb + tig];
            A1[1] = sf1[(row0 + 8) * PA + kb + tig];
            A1[2] = sf1[ row0      * PA + kb + tig + 4];
            A1[3] = sf1[(row0 + 8) * PA + kb + tig + 4];
            int kl = kk * 8 + tig;
#pragma unroll
            for (int j = 0; j < 16; j++) {
                int n = j * 8 + gid;
                unsigned b0h = swh[n * PB + kl], b1h = swh[n * PB + kl + 4];
                unsigned b0l = swl[n * PB + kl], b1l = swl[n * PB + kl + 4];
                MMA_BF16(acc[j], A0, b0h, b1h);
                MMA_BF16(acc[j], A0, b0l, b1l);
                MMA_BF16(acc[j], A1, b0h, b1h);
            }
        }
    }

    float* out = half ? outD : outS;
    const float* bias = half ? bd : bs;
    int r0 = rowbase + mtile * 16 + gid;     // source row index g
    int r1 = r0 + 8;

    // destination rows + masks
    long long d0 = r0, d1 = r1;
    bool ok0 = r0 < nrows, ok1 = r1 < nrows;
    if (LAYER == 3) {
        int n0 = ok0 ? __ldg(nid + r0) : 0;
        int n1 = ok1 ? __ldg(nid + r1) : 0;
        ok0 = ok0 && (g_map[n0] == r0);
        ok1 = ok1 && (g_map[n1] == r1);
        d0 = n0; d1 = n1;
    }

#pragma unroll
    for (int j = 0; j < 16; j++) {
        int col = j * 8 + tig * 2;
        float b0 = __ldg(bias + col), b1 = __ldg(bias + col + 1);
        if (ok0)
            *(float2*)(out + (size_t)d0 * FD + col) =
                make_float2(acc[j][0] + b0, acc[j][1] + b1);
        if (ok1)
            *(float2*)(out + (size_t)d1 * FD + col) =
                make_float2(acc[j][2] + b0, acc[j][3] + b1);
    }
}

// ---------------- fused per-node GATv2 aggregation --------------------------------
template<int LAYER>
__global__ void __launch_bounds__(256)
k_node(const float* __restrict__ attn, float* __restrict__ out,
       const int* __restrict__ nid, int N)
{
    const float* el  = (LAYER == 1) ? g_el1  : g_el2;
    const float* er  = (LAYER == 1) ? g_er1  : g_er2;
    const int*   off = (LAYER == 1) ? g_off1 : g_off2;
    const int*   csr = (LAYER == 1) ? g_csr1 : g_csr2;

    int v    = (blockIdx.x * blockDim.x + threadIdx.x) >> 5;
    int lane = threadIdx.x & 31;
    if (v >= N) return;

    int i0 = __ldg(off + v), i1 = __ldg(off + v + 1);
    float4 t = ((const float4*)attn)[lane];
    float4 r = ((const float4*)(er + (size_t)v * FD))[lane];

    float4 acc = make_float4(0.f, 0.f, 0.f, 0.f);
    float den = 0.f;

    int i = i0;
    for (; i + 8 <= i1; i += 8) {
        int u[8];
        float4 a[8];
        float p[8];
#pragma unroll
        for (int q = 0; q < 8; q++) u[q] = __ldg(csr + i + q);
#pragma unroll
        for (int q = 0; q < 8; q++)
            a[q] = ldg4_na((const float4*)(el + (size_t)u[q] * FD) + lane);
#pragma unroll
        for (int q = 0; q < 8; q++)
            p[q] = lrelu(a[q].x + r.x, 0.2f) * t.x + lrelu(a[q].y + r.y, 0.2f) * t.y
                 + lrelu(a[q].z + r.z, 0.2f) * t.z + lrelu(a[q].w + r.w, 0.2f) * t.w;
#pragma unroll
        for (int o = 16; o; o >>= 1)
#pragma unroll
            for (int q = 0; q < 8; q++)
                p[q] += __shfl_xor_sync(0xffffffffu, p[q], o);
#pragma unroll
        for (int q = 0; q < 8; q++) {
            float e = expf(p[q]);
            den += e;
            acc.x += e * a[q].x; acc.y += e * a[q].y;
            acc.z += e * a[q].z; acc.w += e * a[q].w;
        }
    }
    for (; i + 2 <= i1; i += 2) {
        int u0 = __ldg(csr + i), u1 = __ldg(csr + i + 1);
        float4 a0 = ldg4_na((const float4*)(el + (size_t)u0 * FD) + lane);
        float4 a1 = ldg4_na((const float4*)(el + (size_t)u1 * FD) + lane);
        float p0 = lrelu(a0.x + r.x, 0.2f) * t.x + lrelu(a0.y + r.y, 0.2f) * t.y
                 + lrelu(a0.z + r.z, 0.2f) * t.z + lrelu(a0.w + r.w, 0.2f) * t.w;
        float p1 = lrelu(a1.x + r.x, 0.2f) * t.x + lrelu(a1.y + r.y, 0.2f) * t.y
                 + lrelu(a1.z + r.z, 0.2f) * t.z + lrelu(a1.w + r.w, 0.2f) * t.w;
#pragma unroll
        for (int o = 16; o; o >>= 1) {
            p0 += __shfl_xor_sync(0xffffffffu, p0, o);
            p1 += __shfl_xor_sync(0xffffffffu, p1, o);
        }
        float e0 = expf(p0), e1 = expf(p1);
        den += e0 + e1;
        acc.x += e0 * a0.x + e1 * a1.x;
        acc.y += e0 * a0.y + e1 * a1.y;
        acc.z += e0 * a0.z + e1 * a1.z;
        acc.w += e0 * a0.w + e1 * a1.w;
    }
    if (i < i1) {
        int u0 = __ldg(csr + i);
        float4 a0 = ldg4_na((const float4*)(el + (size_t)u0 * FD) + lane);
        float p0 = lrelu(a0.x + r.x, 0.2f) * t.x + lrelu(a0.y + r.y, 0.2f) * t.y
                 + lrelu(a0.z + r.z, 0.2f) * t.z + lrelu(a0.w + r.w, 0.2f) * t.w;
#pragma unroll
        for (int o = 16; o; o >>= 1) p0 += __shfl_xor_sync(0xffffffffu, p0, o);
        float e0 = expf(p0);
        den += e0;
        acc.x += e0 * a0.x; acc.y += e0 * a0.y;
        acc.z += e0 * a0.z; acc.w += e0 * a0.w;
    }

    float inv = (i1 > i0) ? (1.f / den) : 0.f;
    acc.x = lrelu(acc.x * inv, 0.01f);
    acc.y = lrelu(acc.y * inv, 0.01f);
    acc.z = lrelu(acc.z * inv, 0.01f);
    acc.w = lrelu(acc.w * inv, 0.01f);

    if (LAYER == 2) {
        ((float4*)(out + (size_t)v * FD))[lane] = acc;
    } else {
        ((float4*)(g_h1 + (size_t)v * FD))[lane] = acc;
        float sum = acc.x + acc.y + acc.z + acc.w;
#pragma unroll
        for (int o = 16; o; o >>= 1) sum += __shfl_xor_sync(0xffffffffu, sum, o);
        if (lane == 0 && sum != 0.f) g_map[__ldg(nid + v)] = v;
    }
}

// ---------------- launch ------------------------------------------------------------
extern "C" void kernel_launch(void* const* d_in, const int* in_sizes, int n_in,
                              void* d_out, int out_size)
{
    const float* emb     = (const float*)d_in[0];
    const int*   i2u_src = (const int*)d_in[1];
    const int*   i2u_dst = (const int*)d_in[2];
    const int*   i2u_nid = (const int*)d_in[3];
    const int*   soc_src = (const int*)d_in[4];
    const int*   soc_dst = (const int*)d_in[5];
    const float* Ws1 = (const float*)d_in[6];
    const float* bs1 = (const float*)d_in[7];
    const float* Wd1 = (const float*)d_in[8];
    const float* bd1 = (const float*)d_in[9];
    const float* at1 = (const float*)d_in[10];
    const float* Ws2 = (const float*)d_in[11];
    const float* bs2 = (const float*)d_in[12];
    const float* Wd2 = (const float*)d_in[13];
    const float* bd2 = (const float*)d_in[14];
    const float* at2 = (const float*)d_in[15];
    float* out = (float*)d_out;

    const int E1 = in_sizes[1];
    const int E2 = in_sizes[4];
    const int N1 = in_sizes[3];
    const int NS = out_size / FD;

    int *cnt1, *cnt2, *off1, *off2, *csr1, *csr2, *cs1, *cs2;
    cudaGetSymbolAddress((void**)&cnt1, g_cnt1);
    cudaGetSymbolAddress((void**)&cnt2, g_cnt2);
    cudaGetSymbolAddress((void**)&off1, g_off1);
    cudaGetSymbolAddress((void**)&off2, g_off2);
    cudaGetSymbolAddress((void**)&csr1, g_csr1);
    cudaGetSymbolAddress((void**)&csr2, g_csr2);
    cudaGetSymbolAddress((void**)&cs1,  g_csum1);
    cudaGetSymbolAddress((void**)&cs2,  g_csum2);

    static cudaStream_t s1 = nullptr, s2 = nullptr;
    static cudaEvent_t ev0 = nullptr, ev1 = nullptr, ev2 = nullptr,
                       evW = nullptr, ev3 = nullptr;
    if (!s1) {
        cudaStreamCreateWithFlags(&s1, cudaStreamNonBlocking);
        cudaStreamCreateWithFlags(&s2, cudaStreamNonBlocking);
        cudaEventCreateWithFlags(&ev0, cudaEventDisableTiming);
        cudaEventCreateWithFlags(&ev1, cudaEventDisableTiming);
        cudaEventCreateWithFlags(&ev2, cudaEventDisableTiming);
        cudaEventCreateWithFlags(&evW, cudaEventDisableTiming);
        cudaEventCreateWithFlags(&ev3, cudaEventDisableTiming);
        cudaFuncSetAttribute(k_gemm_mma<1>, cudaFuncAttributeMaxDynamicSharedMemorySize, GEMM_SMEM);
        cudaFuncSetAttribute(k_gemm_mma<2>, cudaFuncAttributeMaxDynamicSharedMemorySize, GEMM_SMEM);
        cudaFuncSetAttribute(k_gemm_mma<3>, cudaFuncAttributeMaxDynamicSharedMemorySize, GEMM_SMEM);
    }

    const int ch1 = (N1 + 1023) / 1024;
    const int ch2 = (NS + 1023) / 1024;

    // fork
    cudaEventRecord(ev0, 0);
    cudaStreamWaitEvent(s1, ev0, 0);
    cudaStreamWaitEvent(s2, ev0, 0);

    // main: W split first (everything tensor-side depends on it)
    k_wsplit<<<256, 256>>>(Ws1, Wd1, Ws2, Wd2);
    cudaEventRecord(evW, 0);

    // branch s1: graph-1 CSR + map init, then gemm2-main (emb-only, independent of layer 1)
    k_init1<<<(cNSOC + 255) / 256, 256, 0, s1>>>();
    k_hist<<<(E1 + 255) / 256, 256, 0, s1>>>(i2u_dst, cnt1, E1);
    k_scanA<<<ch1, 1024, 0, s1>>>(cnt1, off1, cs1, N1);
    k_scanB<<<1, 128, 0, s1>>>(cs1, ch1);
    k_scanC<<<(N1 + 255) / 256, 256, 0, s1>>>(off1, cs1, cnt1, N1);
    k_scatter<<<(E1 + 255) / 256, 256, 0, s1>>>(i2u_src, i2u_dst, cnt1, csr1, E1);
    cudaEventRecord(ev1, s1);
    cudaStreamWaitEvent(s1, evW, 0);
    k_gemm_mma<2><<<(NS + 127) / 128, 512, GEMM_SMEM, s1>>>(emb, nullptr, bs2, bd2, NS);
    cudaEventRecord(ev3, s1);

    // branch s2: graph-2 CSR
    k_init2<<<(cNSOC + 255) / 256, 256, 0, s2>>>();
    k_hist<<<(E2 + 255) / 256, 256, 0, s2>>>(soc_dst, cnt2, E2);
    k_scanA<<<ch2, 1024, 0, s2>>>(cnt2, off2, cs2, NS);
    k_scanB<<<1, 128, 0, s2>>>(cs2, ch2);
    k_scanC<<<(NS + 255) / 256, 256, 0, s2>>>(off2, cs2, cnt2, NS);
    k_scatter<<<(E2 + 255) / 256, 256, 0, s2>>>(soc_src, soc_dst, cnt2, csr2, E2);
    cudaEventRecord(ev2, s2);

    // main: layer-1 GEMM, join CSR1(+map init), aggregate layer 1
    k_gemm_mma<1><<<(N1 + 127) / 128, 512, GEMM_SMEM>>>(emb, i2u_nid, bs1, bd1, N1);
    cudaStreamWaitEvent(0, ev1, 0);
    k_node<1><<<(N1 + 7) / 8, 256>>>(at1, nullptr, i2u_nid, N1);

    // fix pass: overwrite el2/er2 rows whose features came from h1 (needs gemm2-main done)
    cudaStreamWaitEvent(0, ev3, 0);
    k_gemm_mma<3><<<(N1 + 127) / 128, 512, GEMM_SMEM>>>(emb, i2u_nid, bs2, bd2, N1);

    // join CSR2, aggregate layer 2 into d_out
    cudaStreamWaitEvent(0, ev2, 0);
    k_node<2><<<(NS + 7) / 8, 256>>>(at2, out, nullptr, NS);
}

// round 8
// speedup vs baseline: 1.0898x; 1.0898x over previous
#include <cuda_runtime.h>
#include <cuda_bf16.h>
#include <cstdint>

#define FD 128
#define F4 32

static const int cNSOC = 100000;
static const int cNI2U = 50000;
static const int cESOC = 1600000;
static const int cEI2U = 800000;

// ---------------- scratch ----------------------------------------------------
__device__ __align__(16) float g_el1[cNI2U * FD];
__device__ __align__(16) float g_er1[cNI2U * FD];
__device__ __align__(16) float g_el2[cNSOC * FD];
__device__ __align__(16) float g_er2[cNSOC * FD];
__device__ __align__(16) float g_h1 [cNI2U * FD];
__device__ __align__(16) __nv_bfloat16 g_wbh[4][FD * FD];  // bf16 hi, transposed [n][k]
__device__ __align__(16) __nv_bfloat16 g_wbl[4][FD * FD];  // bf16 lo, transposed
__device__ int   g_map [cNSOC];
__device__ int   g_cnt1[cNI2U];
__device__ int   g_cnt2[cNSOC];
__device__ int   g_off1[cNI2U + 1];
__device__ int   g_off2[cNSOC + 1];
__device__ int   g_csr1[cEI2U];
__device__ int   g_csr2[cESOC];
__device__ int   g_csum1[64];
__device__ int   g_csum2[128];

__device__ __forceinline__ float lrelu(float x, float s) { return x > 0.f ? x : s * x; }

__device__ __forceinline__ void bf16split2(float x, float y, unsigned& hi, unsigned& lo) {
    __nv_bfloat162 h = __floats2bfloat162_rn(x, y);
    float rx = x - __bfloat162float(__low2bfloat16(h));
    float ry = y - __bfloat162float(__high2bfloat16(h));
    __nv_bfloat162 l = __floats2bfloat162_rn(rx, ry);
    hi = *(unsigned*)&h;
    lo = *(unsigned*)&l;
}

__device__ __forceinline__ float4 ldg4_na(const float4* p) {
    float4 v;
    asm volatile("ld.global.nc.L1::no_allocate.v4.f32 {%0,%1,%2,%3}, [%4];"
                 : "=f"(v.x), "=f"(v.y), "=f"(v.z), "=f"(v.w) : "l"(p));
    return v;
}

// ---------------- init ---------------------------------------------------------
__global__ void k_init1() {
    int i = blockIdx.x * blockDim.x + threadIdx.x;
    if (i < cNSOC) g_map[i] = -1;
    if (i < cNI2U) g_cnt1[i] = 0;
    if (i == 0) g_off1[0] = 0;
}
__global__ void k_init2() {
    int i = blockIdx.x * blockDim.x + threadIdx.x;
    if (i < cNSOC) g_cnt2[i] = 0;
    if (i == 0) g_off2[0] = 0;
}

// ---------------- W split: fp32 [k][n] -> bf16 hi/lo transposed [n][k] ---------
__global__ void k_wsplit(const float* __restrict__ W0, const float* __restrict__ W1,
                         const float* __restrict__ W2, const float* __restrict__ W3) {
    int i = blockIdx.x * blockDim.x + threadIdx.x;
    int m = i >> 14, idx = i & 16383;
    int n = idx >> 7, k = idx & 127;
    const float* W = (m == 0) ? W0 : (m == 1) ? W1 : (m == 2) ? W2 : W3;
    float v = __ldg(W + k * FD + n);
    __nv_bfloat16 h = __float2bfloat16_rn(v);
    g_wbh[m][n * FD + k] = h;
    g_wbl[m][n * FD + k] = __float2bfloat16_rn(v - __bfloat162float(h));
}

// ---------------- CSR build ------------------------------------------------------
__global__ void k_hist(const int* __restrict__ dst, int* __restrict__ cnt, int E) {
    int e = blockIdx.x * blockDim.x + threadIdx.x;
    if (e < E) atomicAdd(cnt + __ldg(dst + e), 1);
}

__global__ void k_scanA(const int* __restrict__ cnt, int* __restrict__ off,
                        int* __restrict__ csum, int N) {
    __shared__ int sh[1024];
    int t = threadIdx.x;
    int i = blockIdx.x * 1024 + t;
    sh[t] = (i < N) ? cnt[i] : 0;
    __syncthreads();
#pragma unroll
    for (int d = 1; d < 1024; d <<= 1) {
        int add = (t >= d) ? sh[t - d] : 0;
        __syncthreads();
        sh[t] += add;
        __syncthreads();
    }
    if (i < N) off[i + 1] = sh[t];
    if (t == 1023) csum[blockIdx.x] = sh[t];
}

__global__ void k_scanB(int* __restrict__ c, int n) {
    __shared__ int sh[128];
    int t = threadIdx.x;
    sh[t] = (t < n) ? c[t] : 0;
    __syncthreads();
#pragma unroll
    for (int d = 1; d < 128; d <<= 1) {
        int add = (t >= d) ? sh[t - d] : 0;
        __syncthreads();
        sh[t] += add;
        __syncthreads();
    }
    if (t < n) c[t] = sh[t];
}

__global__ void k_scanC(int* __restrict__ off, const int* __restrict__ csum,
                        int* __restrict__ cur, int N) {
    int i = blockIdx.x * blockDim.x + threadIdx.x;
    if (i >= N) return;
    int ch = i >> 10;
    int c = cur[i];
    int inc = off[i + 1] + (ch > 0 ? csum[ch - 1] : 0);
    off[i + 1] = inc;
    cur[i] = inc - c;
}

__global__ void k_scatter(const int* __restrict__ src, const int* __restrict__ dst,
                          int* __restrict__ cur, int* __restrict__ csr, int E) {
    int e = blockIdx.x * blockDim.x + threadIdx.x;
    if (e >= E) return;
    int pos = atomicAdd(cur + __ldg(dst + e), 1);
    csr[pos] = __ldg(src + e);
}

// ---------------- tensor-core dual GEMM (bf16x3 split) ---------------------------
// LAYER 1: feat = emb[nid[g]]                         -> el1/er1
// LAYER 2: feat = map[g]>=0 ? h1[map[g]] : emb[g]     -> el2/er2
#define PA 66
#define PB 20
#define GEMM_SMEM ((2 * 128 * PA + 4 * 128 * PB) * 4)

#define MMA_BF16(ACC, A, B0, B1)                                                \
    asm volatile("mma.sync.aligned.m16n8k16.row.col.f32.bf16.bf16.f32 "         \
                 "{%0,%1,%2,%3}, {%4,%5,%6,%7}, {%8,%9}, {%0,%1,%2,%3};"        \
                 : "+f"(ACC[0]), "+f"(ACC[1]), "+f"(ACC[2]), "+f"(ACC[3])       \
                 : "r"(A[0]), "r"(A[1]), "r"(A[2]), "r"(A[3]), "r"(B0), "r"(B1))

template<int LAYER>
__global__ void __launch_bounds__(512, 1)
k_gemm_mma(const float* __restrict__ emb, const int* __restrict__ nid,
           const float* __restrict__ bs, const float* __restrict__ bd, int nrows)
{
    extern __shared__ unsigned smu[];
    unsigned* sf0 = smu;
    unsigned* sf1 = sf0 + 128 * PA;
    unsigned* sw  = sf1 + 128 * PA;

    const int mS = (LAYER == 1) ? 0 : 2;
    const int mD = (LAYER == 1) ? 1 : 3;
    float* outS = (LAYER == 1) ? g_el1 : g_el2;
    float* outD = (LAYER == 1) ? g_er1 : g_er2;

    const int tid = threadIdx.x;
    const int rowbase = blockIdx.x * 128;

    for (int s = tid; s < 128 * F4; s += 512) {
        int r = s >> 5, c4 = s & 31;
        int g = rowbase + r;
        float4 v = make_float4(0.f, 0.f, 0.f, 0.f);
        if (g < nrows) {
            const float* p;
            if (LAYER == 1) {
                p = emb + (size_t)__ldg(nid + g) * FD;
            } else {
                int mj = g_map[g];
                p = (mj >= 0) ? (g_h1 + (size_t)mj * FD) : (emb + (size_t)g * FD);
            }
            v = ((const float4*)p)[c4];
        }
        unsigned h0, l0, h1v, l1;
        bf16split2(v.x, v.y, h0, l0);
        bf16split2(v.z, v.w, h1v, l1);
        int w = r * PA + c4 * 2;
        sf0[w] = h0; sf0[w + 1] = h1v;
        sf1[w] = l0; sf1[w + 1] = l1;
    }

    const int lane = tid & 31, warp = tid >> 5;
    const int mtile = warp >> 1, half = warp & 1;
    const int gid = lane >> 2, tig = lane & 3;

    unsigned* swh = sw + (half * 2 + 0) * 128 * PB;
    unsigned* swl = sw + (half * 2 + 1) * 128 * PB;

    float acc[16][4];
#pragma unroll
    for (int j = 0; j < 16; j++)
#pragma unroll
        for (int q = 0; q < 4; q++) acc[j][q] = 0.f;

    const __nv_bfloat16* wbhS = g_wbh[mS];
    const __nv_bfloat16* wblS = g_wbl[mS];
    const __nv_bfloat16* wbhD = g_wbh[mD];
    const __nv_bfloat16* wblD = g_wbl[mD];

    for (int ch = 0; ch < 4; ch++) {
        __syncthreads();
        {
            int n = tid >> 2, q = tid & 3;
            int gsrc = (n * FD + ch * 32) / 8 + q;
            int wdst = n * PB + q * 4;
            ((uint4*)(sw + 0 * 128 * PB + wdst))[0] = ((const uint4*)wbhS)[gsrc];
            ((uint4*)(sw + 1 * 128 * PB + wdst))[0] = ((const uint4*)wblS)[gsrc];
            ((uint4*)(sw + 2 * 128 * PB + wdst))[0] = ((const uint4*)wbhD)[gsrc];
            ((uint4*)(sw + 3 * 128 * PB + wdst))[0] = ((const uint4*)wblD)[gsrc];
        }
        __syncthreads();

#pragma unroll
        for (int kk = 0; kk < 2; kk++) {
            int kb = ch * 16 + kk * 8;
            int row0 = mtile * 16 + gid;
            unsigned A0[4], A1[4];
            A0[0] = sf0[ row0      * PA + kb + tig];
            A0[1] = sf0[(row0 + 8) * PA + kb + tig];
            A0[2] = sf0[ row0      * PA + kb + tig + 4];
            A0[3] = sf0[(row0 + 8) * PA + kb + tig + 4];
            A1[0] = sf1[ row0      * PA + kb + tig];
            A1[1] = sf1[(row0 + 8) * PA + kb + tig];
            A1[2] = sf1[ row0      * PA + kb + tig + 4];
            A1[3] = sf1[(row0 + 8) * PA + kb + tig + 4];
            int kl = kk * 8 + tig;
#pragma unroll
            for (int j = 0; j < 16; j++) {
                int n = j * 8 + gid;
                unsigned b0h = swh[n * PB + kl], b1h = swh[n * PB + kl + 4];
                unsigned b0l = swl[n * PB + kl], b1l = swl[n * PB + kl + 4];
                MMA_BF16(acc[j], A0, b0h, b1h);
                MMA_BF16(acc[j], A0, b0l, b1l);
                MMA_BF16(acc[j], A1, b0h, b1h);
            }
        }
    }

    float* out = half ? outD : outS;
    const float* bias = half ? bd : bs;
    int r0 = rowbase + mtile * 16 + gid;
#pragma unroll
    for (int j = 0; j < 16; j++) {
        int col = j * 8 + tig * 2;
        float b0 = __ldg(bias + col), b1 = __ldg(bias + col + 1);
        if (r0 < nrows) {
            *(float2*)(out + (size_t)r0 * FD + col) =
                make_float2(acc[j][0] + b0, acc[j][1] + b1);
        }
        if (r0 + 8 < nrows) {
            *(float2*)(out + (size_t)(r0 + 8) * FD + col) =
                make_float2(acc[j][2] + b0, acc[j][3] + b1);
        }
    }
}

// ---------------- fused per-node GATv2 aggregation --------------------------------
template<int LAYER>
__global__ void __launch_bounds__(256)
k_node(const float* __restrict__ attn, float* __restrict__ out,
       const int* __restrict__ nid, int N)
{
    const float* el  = (LAYER == 1) ? g_el1  : g_el2;
    const float* er  = (LAYER == 1) ? g_er1  : g_er2;
    const int*   off = (LAYER == 1) ? g_off1 : g_off2;
    const int*   csr = (LAYER == 1) ? g_csr1 : g_csr2;

    int v    = (blockIdx.x * blockDim.x + threadIdx.x) >> 5;
    int lane = threadIdx.x & 31;
    if (v >= N) return;

    int i0 = __ldg(off + v), i1 = __ldg(off + v + 1);
    float4 t = ((const float4*)attn)[lane];
    float4 r = ((const float4*)(er + (size_t)v * FD))[lane];

    float4 acc = make_float4(0.f, 0.f, 0.f, 0.f);
    float den = 0.f;

    int i = i0;
    for (; i + 8 <= i1; i += 8) {
        int u[8];
        float4 a[8];
        float p[8];
#pragma unroll
        for (int q = 0; q < 8; q++) u[q] = __ldg(csr + i + q);
#pragma unroll
        for (int q = 0; q < 8; q++)
            a[q] = ldg4_na((const float4*)(el + (size_t)u[q] * FD) + lane);
#pragma unroll
        for (int q = 0; q < 8; q++)
            p[q] = lrelu(a[q].x + r.x, 0.2f) * t.x + lrelu(a[q].y + r.y, 0.2f) * t.y
                 + lrelu(a[q].z + r.z, 0.2f) * t.z + lrelu(a[q].w + r.w, 0.2f) * t.w;
#pragma unroll
        for (int o = 16; o; o >>= 1)
#pragma unroll
            for (int q = 0; q < 8; q++)
                p[q] += __shfl_xor_sync(0xffffffffu, p[q], o);
#pragma unroll
        for (int q = 0; q < 8; q++) {
            float e = __expf(p[q]);
            den += e;
            acc.x += e * a[q].x; acc.y += e * a[q].y;
            acc.z += e * a[q].z; acc.w += e * a[q].w;
        }
    }
    for (; i + 2 <= i1; i += 2) {
        int u0 = __ldg(csr + i), u1 = __ldg(csr + i + 1);
        float4 a0 = ldg4_na((const float4*)(el + (size_t)u0 * FD) + lane);
        float4 a1 = ldg4_na((const float4*)(el + (size_t)u1 * FD) + lane);
        float p0 = lrelu(a0.x + r.x, 0.2f) * t.x + lrelu(a0.y + r.y, 0.2f) * t.y
                 + lrelu(a0.z + r.z, 0.2f) * t.z + lrelu(a0.w + r.w, 0.2f) * t.w;
        float p1 = lrelu(a1.x + r.x, 0.2f) * t.x + lrelu(a1.y + r.y, 0.2f) * t.y
                 + lrelu(a1.z + r.z, 0.2f) * t.z + lrelu(a1.w + r.w, 0.2f) * t.w;
#pragma unroll
        for (int o = 16; o; o >>= 1) {
            p0 += __shfl_xor_sync(0xffffffffu, p0, o);
            p1 += __shfl_xor_sync(0xffffffffu, p1, o);
        }
        float e0 = __expf(p0), e1 = __expf(p1);
        den += e0 + e1;
        acc.x += e0 * a0.x + e1 * a1.x;
        acc.y += e0 * a0.y + e1 * a1.y;
        acc.z += e0 * a0.z + e1 * a1.z;
        acc.w += e0 * a0.w + e1 * a1.w;
    }
    if (i < i1) {
        int u0 = __ldg(csr + i);
        float4 a0 = ldg4_na((const float4*)(el + (size_t)u0 * FD) + lane);
        float p0 = lrelu(a0.x + r.x, 0.2f) * t.x + lrelu(a0.y + r.y, 0.2f) * t.y
                 + lrelu(a0.z + r.z, 0.2f) * t.z + lrelu(a0.w + r.w, 0.2f) * t.w;
#pragma unroll
        for (int o = 16; o; o >>= 1) p0 += __shfl_xor_sync(0xffffffffu, p0, o);
        float e0 = __expf(p0);
        den += e0;
        acc.x += e0 * a0.x; acc.y += e0 * a0.y;
        acc.z += e0 * a0.z; acc.w += e0 * a0.w;
    }

    float inv = (i1 > i0) ? (1.f / den) : 0.f;
    acc.x = lrelu(acc.x * inv, 0.01f);
    acc.y = lrelu(acc.y * inv, 0.01f);
    acc.z = lrelu(acc.z * inv, 0.01f);
    acc.w = lrelu(acc.w * inv, 0.01f);

    if (LAYER == 2) {
        ((float4*)(out + (size_t)v * FD))[lane] = acc;
    } else {
        ((float4*)(g_h1 + (size_t)v * FD))[lane] = acc;
        float sum = acc.x + acc.y + acc.z + acc.w;
#pragma unroll
        for (int o = 16; o; o >>= 1) sum += __shfl_xor_sync(0xffffffffu, sum, o);
        if (lane == 0 && sum != 0.f) g_map[__ldg(nid + v)] = v;
    }
}

// ---------------- launch ------------------------------------------------------------
extern "C" void kernel_launch(void* const* d_in, const int* in_sizes, int n_in,
                              void* d_out, int out_size)
{
    const float* emb     = (const float*)d_in[0];
    const int*   i2u_src = (const int*)d_in[1];
    const int*   i2u_dst = (const int*)d_in[2];
    const int*   i2u_nid = (const int*)d_in[3];
    const int*   soc_src = (const int*)d_in[4];
    const int*   soc_dst = (const int*)d_in[5];
    const float* Ws1 = (const float*)d_in[6];
    const float* bs1 = (const float*)d_in[7];
    const float* Wd1 = (const float*)d_in[8];
    const float* bd1 = (const float*)d_in[9];
    const float* at1 = (const float*)d_in[10];
    const float* Ws2 = (const float*)d_in[11];
    const float* bs2 = (const float*)d_in[12];
    const float* Wd2 = (const float*)d_in[13];
    const float* bd2 = (const float*)d_in[14];
    const float* at2 = (const float*)d_in[15];
    float* out = (float*)d_out;

    const int E1 = in_sizes[1];
    const int E2 = in_sizes[4];
    const int N1 = in_sizes[3];
    const int NS = out_size / FD;

    int *cnt1, *cnt2, *off1, *off2, *csr1, *csr2, *cs1, *cs2;
    cudaGetSymbolAddress((void**)&cnt1, g_cnt1);
    cudaGetSymbolAddress((void**)&cnt2, g_cnt2);
    cudaGetSymbolAddress((void**)&off1, g_off1);
    cudaGetSymbolAddress((void**)&off2, g_off2);
    cudaGetSymbolAddress((void**)&csr1, g_csr1);
    cudaGetSymbolAddress((void**)&csr2, g_csr2);
    cudaGetSymbolAddress((void**)&cs1,  g_csum1);
    cudaGetSymbolAddress((void**)&cs2,  g_csum2);

    static cudaStream_t s1 = nullptr, s2 = nullptr;
    static cudaEvent_t ev0 = nullptr, ev1 = nullptr, ev2 = nullptr;
    if (!s1) {
        cudaStreamCreateWithFlags(&s1, cudaStreamNonBlocking);
        cudaStreamCreateWithFlags(&s2, cudaStreamNonBlocking);
        cudaEventCreateWithFlags(&ev0, cudaEventDisableTiming);
        cudaEventCreateWithFlags(&ev1, cudaEventDisableTiming);
        cudaEventCreateWithFlags(&ev2, cudaEventDisableTiming);
        cudaFuncSetAttribute(k_gemm_mma<1>, cudaFuncAttributeMaxDynamicSharedMemorySize, GEMM_SMEM);
        cudaFuncSetAttribute(k_gemm_mma<2>, cudaFuncAttributeMaxDynamicSharedMemorySize, GEMM_SMEM);
    }

    const int ch1 = (N1 + 1023) / 1024;
    const int ch2 = (NS + 1023) / 1024;

    // fork side branches off the (captured) main stream
    cudaEventRecord(ev0, 0);
    cudaStreamWaitEvent(s1, ev0, 0);
    cudaStreamWaitEvent(s2, ev0, 0);

    // branch s1: graph-1 CSR + map init
    k_init1<<<(cNSOC + 255) / 256, 256, 0, s1>>>();
    k_hist<<<(E1 + 255) / 256, 256, 0, s1>>>(i2u_dst, cnt1, E1);
    k_scanA<<<ch1, 1024, 0, s1>>>(cnt1, off1, cs1, N1);
    k_scanB<<<1, 128, 0, s1>>>(cs1, ch1);
    k_scanC<<<(N1 + 255) / 256, 256, 0, s1>>>(off1, cs1, cnt1, N1);
    k_scatter<<<(E1 + 255) / 256, 256, 0, s1>>>(i2u_src, i2u_dst, cnt1, csr1, E1);
    cudaEventRecord(ev1, s1);

    // branch s2: graph-2 CSR
    k_init2<<<(cNSOC + 255) / 256, 256, 0, s2>>>();
    k_hist<<<(E2 + 255) / 256, 256, 0, s2>>>(soc_dst, cnt2, E2);
    k_scanA<<<ch2, 1024, 0, s2>>>(cnt2, off2, cs2, NS);
    k_scanB<<<1, 128, 0, s2>>>(cs2, ch2);
    k_scanC<<<(NS + 255) / 256, 256, 0, s2>>>(off2, cs2, cnt2, NS);
    k_scatter<<<(E2 + 255) / 256, 256, 0, s2>>>(soc_src, soc_dst, cnt2, csr2, E2);
    cudaEventRecord(ev2, s2);

    // main: W split, layer-1 GEMM
    k_wsplit<<<256, 256>>>(Ws1, Wd1, Ws2, Wd2);
    k_gemm_mma<1><<<(N1 + 127) / 128, 512, GEMM_SMEM>>>(emb, i2u_nid, bs1, bd1, N1);

    // join graph-1 CSR, aggregate layer 1
    cudaStreamWaitEvent(0, ev1, 0);
    k_node<1><<<(N1 + 7) / 8, 256>>>(at1, nullptr, i2u_nid, N1);

    // layer-2 GEMM (features = map>=0 ? h1 : emb)
    k_gemm_mma<2><<<(NS + 127) / 128, 512, GEMM_SMEM>>>(emb, nullptr, bs2, bd2, NS);

    // join graph-2 CSR, aggregate layer 2 into d_out
    cudaStreamWaitEvent(0, ev2, 0);
    k_node<2><<<(NS + 7) / 8, 256>>>(at2, out, nullptr, NS);
}

// round 9
// speedup vs baseline: 1.2973x; 1.1904x over previous
#include <cuda_runtime.h>
#include <cuda_bf16.h>
#include <cstdint>

#define FD 128
#define F4 32

static const int cNSOC = 100000;
static const int cNI2U = 50000;
static const int cESOC = 1600000;
static const int cEI2U = 800000;

// ---------------- scratch ----------------------------------------------------
__device__ __align__(16) float g_el1[cNI2U * FD];
__device__ __align__(16) float g_er1[cNI2U * FD];
__device__ __align__(16) float g_el2[cNSOC * FD];
__device__ __align__(16) float g_er2[cNSOC * FD];
__device__ __align__(16) float g_h1 [cNI2U * FD];
__device__ __align__(16) __nv_bfloat16 g_wbh[4][FD * FD];  // bf16 hi, transposed [n][k]
__device__ __align__(16) __nv_bfloat16 g_wbl[4][FD * FD];  // bf16 lo, transposed
__device__ int   g_map [cNSOC];
__device__ int   g_cnt1[cNI2U];
__device__ int   g_cnt2[cNSOC];
__device__ int   g_off1[cNI2U + 1];
__device__ int   g_off2[cNSOC + 1];
__device__ int   g_csr1[cEI2U];
__device__ int   g_csr2[cESOC];
__device__ int   g_csum1[64];
__device__ int   g_csum2[128];

__device__ __forceinline__ float lrelu(float x, float s) { return x > 0.f ? x : s * x; }

__device__ __forceinline__ void bf16split2(float x, float y, unsigned& hi, unsigned& lo) {
    __nv_bfloat162 h = __floats2bfloat162_rn(x, y);
    float rx = x - __bfloat162float(__low2bfloat16(h));
    float ry = y - __bfloat162float(__high2bfloat16(h));
    __nv_bfloat162 l = __floats2bfloat162_rn(rx, ry);
    hi = *(unsigned*)&h;
    lo = *(unsigned*)&l;
}

__device__ __forceinline__ float4 ldg4_na(const float4* p) {
    float4 v;
    asm volatile("ld.global.nc.L1::no_allocate.v4.f32 {%0,%1,%2,%3}, [%4];"
                 : "=f"(v.x), "=f"(v.y), "=f"(v.z), "=f"(v.w) : "l"(p));
    return v;
}

// ---------------- init ---------------------------------------------------------
__global__ void k_init1() {
    int i = blockIdx.x * blockDim.x + threadIdx.x;
    if (i < cNSOC) g_map[i] = -1;
    if (i < cNI2U) g_cnt1[i] = 0;
    if (i == 0) g_off1[0] = 0;
}
__global__ void k_init2() {
    int i = blockIdx.x * blockDim.x + threadIdx.x;
    if (i < cNSOC) g_cnt2[i] = 0;
    if (i == 0) g_off2[0] = 0;
}

// ---------------- W split: fp32 [k][n] -> bf16 hi/lo transposed [n][k] ---------
__global__ void k_wsplit(const float* __restrict__ W0, const float* __restrict__ W1,
                         const float* __restrict__ W2, const float* __restrict__ W3) {
    int i = blockIdx.x * blockDim.x + threadIdx.x;
    int m = i >> 14, idx = i & 16383;
    int n = idx >> 7, k = idx & 127;
    const float* W = (m == 0) ? W0 : (m == 1) ? W1 : (m == 2) ? W2 : W3;
    float v = __ldg(W + k * FD + n);
    __nv_bfloat16 h = __float2bfloat16_rn(v);
    g_wbh[m][n * FD + k] = h;
    g_wbl[m][n * FD + k] = __float2bfloat16_rn(v - __bfloat162float(h));
}

// ---------------- CSR build ------------------------------------------------------
__global__ void k_hist(const int* __restrict__ dst, int* __restrict__ cnt, int E) {
    int e = blockIdx.x * blockDim.x + threadIdx.x;
    if (e < E) atomicAdd(cnt + __ldg(dst + e), 1);
}

__global__ void k_scanA(const int* __restrict__ cnt, int* __restrict__ off,
                        int* __restrict__ csum, int N) {
    __shared__ int sh[1024];
    int t = threadIdx.x;
    int i = blockIdx.x * 1024 + t;
    sh[t] = (i < N) ? cnt[i] : 0;
    __syncthreads();
#pragma unroll
    for (int d = 1; d < 1024; d <<= 1) {
        int add = (t >= d) ? sh[t - d] : 0;
        __syncthreads();
        sh[t] += add;
        __syncthreads();
    }
    if (i < N) off[i + 1] = sh[t];
    if (t == 1023) csum[blockIdx.x] = sh[t];
}

__global__ void k_scanB(int* __restrict__ c, int n) {
    __shared__ int sh[128];
    int t = threadIdx.x;
    sh[t] = (t < n) ? c[t] : 0;
    __syncthreads();
#pragma unroll
    for (int d = 1; d < 128; d <<= 1) {
        int add = (t >= d) ? sh[t - d] : 0;
        __syncthreads();
        sh[t] += add;
        __syncthreads();
    }
    if (t < n) c[t] = sh[t];
}

__global__ void k_scanC(int* __restrict__ off, const int* __restrict__ csum,
                        int* __restrict__ cur, int N) {
    int i = blockIdx.x * blockDim.x + threadIdx.x;
    if (i >= N) return;
    int ch = i >> 10;
    int c = cur[i];
    int inc = off[i + 1] + (ch > 0 ? csum[ch - 1] : 0);
    off[i + 1] = inc;
    cur[i] = inc - c;
}

__global__ void k_scatter(const int* __restrict__ src, const int* __restrict__ dst,
                          int* __restrict__ cur, int* __restrict__ csr, int E) {
    int e = blockIdx.x * blockDim.x + threadIdx.x;
    if (e >= E) return;
    int pos = atomicAdd(cur + __ldg(dst + e), 1);
    csr[pos] = __ldg(src + e);
}

// ---------------- tensor-core dual GEMM (bf16x3 split) ---------------------------
// LAYER 1: feat = emb[nid[g]]                         -> el1/er1
// LAYER 2: feat = map[g]>=0 ? h1[map[g]] : emb[g]     -> el2/er2
#define PA 66
#define PB 20
#define GEMM_SMEM ((2 * 128 * PA + 4 * 128 * PB) * 4)

#define MMA_BF16(ACC, A, B0, B1)                                                \
    asm volatile("mma.sync.aligned.m16n8k16.row.col.f32.bf16.bf16.f32 "         \
                 "{%0,%1,%2,%3}, {%4,%5,%6,%7}, {%8,%9}, {%0,%1,%2,%3};"        \
                 : "+f"(ACC[0]), "+f"(ACC[1]), "+f"(ACC[2]), "+f"(ACC[3])       \
                 : "r"(A[0]), "r"(A[1]), "r"(A[2]), "r"(A[3]), "r"(B0), "r"(B1))

template<int LAYER>
__global__ void __launch_bounds__(512, 1)
k_gemm_mma(const float* __restrict__ emb, const int* __restrict__ nid,
           const float* __restrict__ bs, const float* __restrict__ bd, int nrows)
{
    extern __shared__ unsigned smu[];
    unsigned* sf0 = smu;
    unsigned* sf1 = sf0 + 128 * PA;
    unsigned* sw  = sf1 + 128 * PA;

    const int mS = (LAYER == 1) ? 0 : 2;
    const int mD = (LAYER == 1) ? 1 : 3;
    float* outS = (LAYER == 1) ? g_el1 : g_el2;
    float* outD = (LAYER == 1) ? g_er1 : g_er2;

    const int tid = threadIdx.x;
    const int rowbase = blockIdx.x * 128;

    for (int s = tid; s < 128 * F4; s += 512) {
        int r = s >> 5, c4 = s & 31;
        int g = rowbase + r;
        float4 v = make_float4(0.f, 0.f, 0.f, 0.f);
        if (g < nrows) {
            const float* p;
            if (LAYER == 1) {
                p = emb + (size_t)__ldg(nid + g) * FD;
            } else {
                int mj = g_map[g];
                p = (mj >= 0) ? (g_h1 + (size_t)mj * FD) : (emb + (size_t)g * FD);
            }
            v = ((const float4*)p)[c4];
        }
        unsigned h0, l0, h1v, l1;
        bf16split2(v.x, v.y, h0, l0);
        bf16split2(v.z, v.w, h1v, l1);
        int w = r * PA + c4 * 2;
        sf0[w] = h0; sf0[w + 1] = h1v;
        sf1[w] = l0; sf1[w + 1] = l1;
    }

    const int lane = tid & 31, warp = tid >> 5;
    const int mtile = warp >> 1, half = warp & 1;
    const int gid = lane >> 2, tig = lane & 3;

    unsigned* swh = sw + (half * 2 + 0) * 128 * PB;
    unsigned* swl = sw + (half * 2 + 1) * 128 * PB;

    float acc[16][4];
#pragma unroll
    for (int j = 0; j < 16; j++)
#pragma unroll
        for (int q = 0; q < 4; q++) acc[j][q] = 0.f;

    const __nv_bfloat16* wbhS = g_wbh[mS];
    const __nv_bfloat16* wblS = g_wbl[mS];
    const __nv_bfloat16* wbhD = g_wbh[mD];
    const __nv_bfloat16* wblD = g_wbl[mD];

    for (int ch = 0; ch < 4; ch++) {
        __syncthreads();
        {
            int n = tid >> 2, q = tid & 3;
            int gsrc = (n * FD + ch * 32) / 8 + q;
            int wdst = n * PB + q * 4;
            ((uint4*)(sw + 0 * 128 * PB + wdst))[0] = ((const uint4*)wbhS)[gsrc];
            ((uint4*)(sw + 1 * 128 * PB + wdst))[0] = ((const uint4*)wblS)[gsrc];
            ((uint4*)(sw + 2 * 128 * PB + wdst))[0] = ((const uint4*)wbhD)[gsrc];
            ((uint4*)(sw + 3 * 128 * PB + wdst))[0] = ((const uint4*)wblD)[gsrc];
        }
        __syncthreads();

#pragma unroll
        for (int kk = 0; kk < 2; kk++) {
            int kb = ch * 16 + kk * 8;
            int row0 = mtile * 16 + gid;
            unsigned A0[4], A1[4];
            A0[0] = sf0[ row0      * PA + kb + tig];
            A0[1] = sf0[(row0 + 8) * PA + kb + tig];
            A0[2] = sf0[ row0      * PA + kb + tig + 4];
            A0[3] = sf0[(row0 + 8) * PA + kb + tig + 4];
            A1[0] = sf1[ row0      * PA + kb + tig];
            A1[1] = sf1[(row0 + 8) * PA + kb + tig];
            A1[2] = sf1[ row0      * PA + kb + tig + 4];
            A1[3] = sf1[(row0 + 8) * PA + kb + tig + 4];
            int kl = kk * 8 + tig;
#pragma unroll
            for (int j = 0; j < 16; j++) {
                int n = j * 8 + gid;
                unsigned b0h = swh[n * PB + kl], b1h = swh[n * PB + kl + 4];
                unsigned b0l = swl[n * PB + kl], b1l = swl[n * PB + kl + 4];
                MMA_BF16(acc[j], A0, b0h, b1h);
                MMA_BF16(acc[j], A0, b0l, b1l);
                MMA_BF16(acc[j], A1, b0h, b1h);
            }
        }
    }

    float* out = half ? outD : outS;
    const float* bias = half ? bd : bs;
    int r0 = rowbase + mtile * 16 + gid;
#pragma unroll
    for (int j = 0; j < 16; j++) {
        int col = j * 8 + tig * 2;
        float b0 = __ldg(bias + col), b1 = __ldg(bias + col + 1);
        if (r0 < nrows) {
            *(float2*)(out + (size_t)r0 * FD + col) =
                make_float2(acc[j][0] + b0, acc[j][1] + b1);
        }
        if (r0 + 8 < nrows) {
            *(float2*)(out + (size_t)(r0 + 8) * FD + col) =
                make_float2(acc[j][2] + b0, acc[j][3] + b1);
        }
    }
}

// ---------------- fused per-node GATv2 aggregation (4-edge unroll) ----------------
template<int LAYER>
__global__ void __launch_bounds__(256)
k_node(const float* __restrict__ attn, float* __restrict__ out,
       const int* __restrict__ nid, int N)
{
    const float* el  = (LAYER == 1) ? g_el1  : g_el2;
    const float* er  = (LAYER == 1) ? g_er1  : g_er2;
    const int*   off = (LAYER == 1) ? g_off1 : g_off2;
    const int*   csr = (LAYER == 1) ? g_csr1 : g_csr2;

    int v    = (blockIdx.x * blockDim.x + threadIdx.x) >> 5;
    int lane = threadIdx.x & 31;
    if (v >= N) return;

    int i0 = __ldg(off + v), i1 = __ldg(off + v + 1);
    float4 t = ((const float4*)attn)[lane];
    float4 r = ((const float4*)(er + (size_t)v * FD))[lane];

    float4 acc = make_float4(0.f, 0.f, 0.f, 0.f);
    float den = 0.f;

    int i = i0;
    for (; i + 4 <= i1; i += 4) {
        int u0 = __ldg(csr + i),     u1 = __ldg(csr + i + 1);
        int u2 = __ldg(csr + i + 2), u3 = __ldg(csr + i + 3);
        float4 a0 = ldg4_na((const float4*)(el + (size_t)u0 * FD) + lane);
        float4 a1 = ldg4_na((const float4*)(el + (size_t)u1 * FD) + lane);
        float4 a2 = ldg4_na((const float4*)(el + (size_t)u2 * FD) + lane);
        float4 a3 = ldg4_na((const float4*)(el + (size_t)u3 * FD) + lane);
        float p0 = lrelu(a0.x + r.x, 0.2f) * t.x + lrelu(a0.y + r.y, 0.2f) * t.y
                 + lrelu(a0.z + r.z, 0.2f) * t.z + lrelu(a0.w + r.w, 0.2f) * t.w;
        float p1 = lrelu(a1.x + r.x, 0.2f) * t.x + lrelu(a1.y + r.y, 0.2f) * t.y
                 + lrelu(a1.z + r.z, 0.2f) * t.z + lrelu(a1.w + r.w, 0.2f) * t.w;
        float p2 = lrelu(a2.x + r.x, 0.2f) * t.x + lrelu(a2.y + r.y, 0.2f) * t.y
                 + lrelu(a2.z + r.z, 0.2f) * t.z + lrelu(a2.w + r.w, 0.2f) * t.w;
        float p3 = lrelu(a3.x + r.x, 0.2f) * t.x + lrelu(a3.y + r.y, 0.2f) * t.y
                 + lrelu(a3.z + r.z, 0.2f) * t.z + lrelu(a3.w + r.w, 0.2f) * t.w;
#pragma unroll
        for (int o = 16; o; o >>= 1) {
            p0 += __shfl_xor_sync(0xffffffffu, p0, o);
            p1 += __shfl_xor_sync(0xffffffffu, p1, o);
            p2 += __shfl_xor_sync(0xffffffffu, p2, o);
            p3 += __shfl_xor_sync(0xffffffffu, p3, o);
        }
        float e0 = __expf(p0), e1 = __expf(p1), e2 = __expf(p2), e3 = __expf(p3);
        den += (e0 + e1) + (e2 + e3);
        acc.x += e0 * a0.x + e1 * a1.x + e2 * a2.x + e3 * a3.x;
        acc.y += e0 * a0.y + e1 * a1.y + e2 * a2.y + e3 * a3.y;
        acc.z += e0 * a0.z + e1 * a1.z + e2 * a2.z + e3 * a3.z;
        acc.w += e0 * a0.w + e1 * a1.w + e2 * a2.w + e3 * a3.w;
    }
    for (; i < i1; i++) {
        int u0 = __ldg(csr + i);
        float4 a0 = ldg4_na((const float4*)(el + (size_t)u0 * FD) + lane);
        float p0 = lrelu(a0.x + r.x, 0.2f) * t.x + lrelu(a0.y + r.y, 0.2f) * t.y
                 + lrelu(a0.z + r.z, 0.2f) * t.z + lrelu(a0.w + r.w, 0.2f) * t.w;
#pragma unroll
        for (int o = 16; o; o >>= 1) p0 += __shfl_xor_sync(0xffffffffu, p0, o);
        float e0 = __expf(p0);
        den += e0;
        acc.x += e0 * a0.x; acc.y += e0 * a0.y;
        acc.z += e0 * a0.z; acc.w += e0 * a0.w;
    }

    float inv = (i1 > i0) ? (1.f / den) : 0.f;
    acc.x = lrelu(acc.x * inv, 0.01f);
    acc.y = lrelu(acc.y * inv, 0.01f);
    acc.z = lrelu(acc.z * inv, 0.01f);
    acc.w = lrelu(acc.w * inv, 0.01f);

    if (LAYER == 2) {
        ((float4*)(out + (size_t)v * FD))[lane] = acc;
    } else {
        ((float4*)(g_h1 + (size_t)v * FD))[lane] = acc;
        float sum = acc.x + acc.y + acc.z + acc.w;
#pragma unroll
        for (int o = 16; o; o >>= 1) sum += __shfl_xor_sync(0xffffffffu, sum, o);
        if (lane == 0 && sum != 0.f) g_map[__ldg(nid + v)] = v;
    }
}

// ---------------- launch ------------------------------------------------------------
extern "C" void kernel_launch(void* const* d_in, const int* in_sizes, int n_in,
                              void* d_out, int out_size)
{
    const float* emb     = (const float*)d_in[0];
    const int*   i2u_src = (const int*)d_in[1];
    const int*   i2u_dst = (const int*)d_in[2];
    const int*   i2u_nid = (const int*)d_in[3];
    const int*   soc_src = (const int*)d_in[4];
    const int*   soc_dst = (const int*)d_in[5];
    const float* Ws1 = (const float*)d_in[6];
    const float* bs1 = (const float*)d_in[7];
    const float* Wd1 = (const float*)d_in[8];
    const float* bd1 = (const float*)d_in[9];
    const float* at1 = (const float*)d_in[10];
    const float* Ws2 = (const float*)d_in[11];
    const float* bs2 = (const float*)d_in[12];
    const float* Wd2 = (const float*)d_in[13];
    const float* bd2 = (const float*)d_in[14];
    const float* at2 = (const float*)d_in[15];
    float* out = (float*)d_out;

    const int E1 = in_sizes[1];
    const int E2 = in_sizes[4];
    const int N1 = in_sizes[3];
    const int NS = out_size / FD;

    int *cnt1, *cnt2, *off1, *off2, *csr1, *csr2, *cs1, *cs2;
    cudaGetSymbolAddress((void**)&cnt1, g_cnt1);
    cudaGetSymbolAddress((void**)&cnt2, g_cnt2);
    cudaGetSymbolAddress((void**)&off1, g_off1);
    cudaGetSymbolAddress((void**)&off2, g_off2);
    cudaGetSymbolAddress((void**)&csr1, g_csr1);
    cudaGetSymbolAddress((void**)&csr2, g_csr2);
    cudaGetSymbolAddress((void**)&cs1,  g_csum1);
    cudaGetSymbolAddress((void**)&cs2,  g_csum2);

    static cudaStream_t s1 = nullptr, s2 = nullptr;
    static cudaEvent_t ev0 = nullptr, ev1 = nullptr, ev2 = nullptr;
    if (!s1) {
        cudaStreamCreateWithFlags(&s1, cudaStreamNonBlocking);
        cudaStreamCreateWithFlags(&s2, cudaStreamNonBlocking);
        cudaEventCreateWithFlags(&ev0, cudaEventDisableTiming);
        cudaEventCreateWithFlags(&ev1, cudaEventDisableTiming);
        cudaEventCreateWithFlags(&ev2, cudaEventDisableTiming);
        cudaFuncSetAttribute(k_gemm_mma<1>, cudaFuncAttributeMaxDynamicSharedMemorySize, GEMM_SMEM);
        cudaFuncSetAttribute(k_gemm_mma<2>, cudaFuncAttributeMaxDynamicSharedMemorySize, GEMM_SMEM);
    }

    const int ch1 = (N1 + 1023) / 1024;
    const int ch2 = (NS + 1023) / 1024;

    // fork side branches off the (captured) main stream
    cudaEventRecord(ev0, 0);
    cudaStreamWaitEvent(s1, ev0, 0);
    cudaStreamWaitEvent(s2, ev0, 0);

    // branch s1: graph-1 CSR + map init
    k_init1<<<(cNSOC + 255) / 256, 256, 0, s1>>>();
    k_hist<<<(E1 + 255) / 256, 256, 0, s1>>>(i2u_dst, cnt1, E1);
    k_scanA<<<ch1, 1024, 0, s1>>>(cnt1, off1, cs1, N1);
    k_scanB<<<1, 128, 0, s1>>>(cs1, ch1);
    k_scanC<<<(N1 + 255) / 256, 256, 0, s1>>>(off1, cs1, cnt1, N1);
    k_scatter<<<(E1 + 255) / 256, 256, 0, s1>>>(i2u_src, i2u_dst, cnt1, csr1, E1);
    cudaEventRecord(ev1, s1);

    // branch s2: graph-2 CSR
    k_init2<<<(cNSOC + 255) / 256, 256, 0, s2>>>();
    k_hist<<<(E2 + 255) / 256, 256, 0, s2>>>(soc_dst, cnt2, E2);
    k_scanA<<<ch2, 1024, 0, s2>>>(cnt2, off2, cs2, NS);
    k_scanB<<<1, 128, 0, s2>>>(cs2, ch2);
    k_scanC<<<(NS + 255) / 256, 256, 0, s2>>>(off2, cs2, cnt2, NS);
    k_scatter<<<(E2 + 255) / 256, 256, 0, s2>>>(soc_src, soc_dst, cnt2, csr2, E2);
    cudaEventRecord(ev2, s2);

    // main: W split, layer-1 GEMM
    k_wsplit<<<256, 256>>>(Ws1, Wd1, Ws2, Wd2);
    k_gemm_mma<1><<<(N1 + 127) / 128, 512, GEMM_SMEM>>>(emb, i2u_nid, bs1, bd1, N1);

    // join graph-1 CSR, aggregate layer 1
    cudaStreamWaitEvent(0, ev1, 0);
    k_node<1><<<(N1 + 7) / 8, 256>>>(at1, nullptr, i2u_nid, N1);

    // layer-2 GEMM (features = map>=0 ? h1 : emb)
    k_gemm_mma<2><<<(NS + 127) / 128, 512, GEMM_SMEM>>>(emb, nullptr, bs2, bd2, NS);

    // join graph-2 CSR, aggregate layer 2 into d_out
    cudaStreamWaitEvent(0, ev2, 0);
    k_node<2><<<(NS + 7) / 8, 256>>>(at2, out, nullptr, NS);
}

// round 10
// speedup vs baseline: 1.3594x; 1.0479x over previous
#include <cuda_runtime.h>
#include <cuda_bf16.h>
#include <cuda_fp16.h>
#include <cstdint>

#define FD 128
#define F4 32

static const int cNSOC = 100000;
static const int cNI2U = 50000;
static const int cESOC = 1600000;
static const int cEI2U = 800000;

// ---------------- scratch ----------------------------------------------------
__device__ __align__(16) __half g_el1h[cNI2U * FD];   // fp16 el (gather-hot)
__device__ __align__(16) __half g_el2h[cNSOC * FD];
__device__ __align__(16) float g_er1[cNI2U * FD];
__device__ __align__(16) float g_er2[cNSOC * FD];
__device__ __align__(16) float g_h1 [cNI2U * FD];
__device__ __align__(16) __nv_bfloat16 g_wbh[4][FD * FD];  // bf16 hi, transposed [n][k]
__device__ __align__(16) __nv_bfloat16 g_wbl[4][FD * FD];  // bf16 lo, transposed
__device__ int   g_map [cNSOC];
__device__ int   g_cnt1[cNI2U];
__device__ int   g_cnt2[cNSOC];
__device__ int   g_off1[cNI2U + 1];
__device__ int   g_off2[cNSOC + 1];
__device__ int   g_csr1[cEI2U];
__device__ int   g_csr2[cESOC];
__device__ int   g_csum1[64];
__device__ int   g_csum2[128];

__device__ __forceinline__ float lrelu(float x, float s) { return x > 0.f ? x : s * x; }

__device__ __forceinline__ void bf16split2(float x, float y, unsigned& hi, unsigned& lo) {
    __nv_bfloat162 h = __floats2bfloat162_rn(x, y);
    float rx = x - __bfloat162float(__low2bfloat16(h));
    float ry = y - __bfloat162float(__high2bfloat16(h));
    __nv_bfloat162 l = __floats2bfloat162_rn(rx, ry);
    hi = *(unsigned*)&h;
    lo = *(unsigned*)&l;
}

// non-allocating 8-byte gather (random rows: no reuse, keep L1 for csr/er)
__device__ __forceinline__ float4 ldh8_na(const __half* row, int lane) {
    unsigned r0, r1;
    asm volatile("ld.global.nc.L1::no_allocate.v2.u32 {%0,%1}, [%2];"
                 : "=r"(r0), "=r"(r1) : "l"(row + lane * 4));
    __half2 h01 = *(__half2*)&r0;
    __half2 h23 = *(__half2*)&r1;
    float2 f01 = __half22float2(h01);
    float2 f23 = __half22float2(h23);
    return make_float4(f01.x, f01.y, f23.x, f23.y);
}

// ---------------- init ---------------------------------------------------------
__global__ void k_init1() {
    int i = blockIdx.x * blockDim.x + threadIdx.x;
    if (i < cNSOC) g_map[i] = -1;
    if (i < cNI2U) g_cnt1[i] = 0;
    if (i == 0) g_off1[0] = 0;
}
__global__ void k_init2() {
    int i = blockIdx.x * blockDim.x + threadIdx.x;
    if (i < cNSOC) g_cnt2[i] = 0;
    if (i == 0) g_off2[0] = 0;
}

// ---------------- W split: fp32 [k][n] -> bf16 hi/lo transposed [n][k] ---------
__global__ void k_wsplit(const float* __restrict__ W0, const float* __restrict__ W1,
                         const float* __restrict__ W2, const float* __restrict__ W3) {
    int i = blockIdx.x * blockDim.x + threadIdx.x;
    int m = i >> 14, idx = i & 16383;
    int n = idx >> 7, k = idx & 127;
    const float* W = (m == 0) ? W0 : (m == 1) ? W1 : (m == 2) ? W2 : W3;
    float v = __ldg(W + k * FD + n);
    __nv_bfloat16 h = __float2bfloat16_rn(v);
    g_wbh[m][n * FD + k] = h;
    g_wbl[m][n * FD + k] = __float2bfloat16_rn(v - __bfloat162float(h));
}

// ---------------- CSR build ------------------------------------------------------
__global__ void k_hist(const int* __restrict__ dst, int* __restrict__ cnt, int E) {
    int e = blockIdx.x * blockDim.x + threadIdx.x;
    if (e < E) atomicAdd(cnt + __ldg(dst + e), 1);
}

__global__ void k_scanA(const int* __restrict__ cnt, int* __restrict__ off,
                        int* __restrict__ csum, int N) {
    __shared__ int sh[1024];
    int t = threadIdx.x;
    int i = blockIdx.x * 1024 + t;
    sh[t] = (i < N) ? cnt[i] : 0;
    __syncthreads();
#pragma unroll
    for (int d = 1; d < 1024; d <<= 1) {
        int add = (t >= d) ? sh[t - d] : 0;
        __syncthreads();
        sh[t] += add;
        __syncthreads();
    }
    if (i < N) off[i + 1] = sh[t];
    if (t == 1023) csum[blockIdx.x] = sh[t];
}

__global__ void k_scanB(int* __restrict__ c, int n) {
    __shared__ int sh[128];
    int t = threadIdx.x;
    sh[t] = (t < n) ? c[t] : 0;
    __syncthreads();
#pragma unroll
    for (int d = 1; d < 128; d <<= 1) {
        int add = (t >= d) ? sh[t - d] : 0;
        __syncthreads();
        sh[t] += add;
        __syncthreads();
    }
    if (t < n) c[t] = sh[t];
}

__global__ void k_scanC(int* __restrict__ off, const int* __restrict__ csum,
                        int* __restrict__ cur, int N) {
    int i = blockIdx.x * blockDim.x + threadIdx.x;
    if (i >= N) return;
    int ch = i >> 10;
    int c = cur[i];
    int inc = off[i + 1] + (ch > 0 ? csum[ch - 1] : 0);
    off[i + 1] = inc;
    cur[i] = inc - c;
}

__global__ void k_scatter(const int* __restrict__ src, const int* __restrict__ dst,
                          int* __restrict__ cur, int* __restrict__ csr, int E) {
    int e = blockIdx.x * blockDim.x + threadIdx.x;
    if (e >= E) return;
    int pos = atomicAdd(cur + __ldg(dst + e), 1);
    csr[pos] = __ldg(src + e);
}

// ---------------- tensor-core dual GEMM (bf16x3 split) ---------------------------
// LAYER 1: feat = emb[nid[g]]                         -> el1h/er1
// LAYER 2: feat = map[g]>=0 ? h1[map[g]] : emb[g]     -> el2h/er2
#define PA 66
#define PB 20
#define GEMM_SMEM ((2 * 128 * PA + 4 * 128 * PB) * 4)

#define MMA_BF16(ACC, A, B0, B1)                                                \
    asm volatile("mma.sync.aligned.m16n8k16.row.col.f32.bf16.bf16.f32 "         \
                 "{%0,%1,%2,%3}, {%4,%5,%6,%7}, {%8,%9}, {%0,%1,%2,%3};"        \
                 : "+f"(ACC[0]), "+f"(ACC[1]), "+f"(ACC[2]), "+f"(ACC[3])       \
                 : "r"(A[0]), "r"(A[1]), "r"(A[2]), "r"(A[3]), "r"(B0), "r"(B1))

template<int LAYER>
__global__ void __launch_bounds__(512, 1)
k_gemm_mma(const float* __restrict__ emb, const int* __restrict__ nid,
           const float* __restrict__ bs, const float* __restrict__ bd, int nrows)
{
    extern __shared__ unsigned smu[];
    unsigned* sf0 = smu;
    unsigned* sf1 = sf0 + 128 * PA;
    unsigned* sw  = sf1 + 128 * PA;

    const int mS = (LAYER == 1) ? 0 : 2;
    const int mD = (LAYER == 1) ? 1 : 3;

    const int tid = threadIdx.x;
    const int rowbase = blockIdx.x * 128;

    for (int s = tid; s < 128 * F4; s += 512) {
        int r = s >> 5, c4 = s & 31;
        int g = rowbase + r;
        float4 v = make_float4(0.f, 0.f, 0.f, 0.f);
        if (g < nrows) {
            const float* p;
            if (LAYER == 1) {
                p = emb + (size_t)__ldg(nid + g) * FD;
            } else {
                int mj = g_map[g];
                p = (mj >= 0) ? (g_h1 + (size_t)mj * FD) : (emb + (size_t)g * FD);
            }
            v = ((const float4*)p)[c4];
        }
        unsigned h0, l0, h1v, l1;
        bf16split2(v.x, v.y, h0, l0);
        bf16split2(v.z, v.w, h1v, l1);
        int w = r * PA + c4 * 2;
        sf0[w] = h0; sf0[w + 1] = h1v;
        sf1[w] = l0; sf1[w + 1] = l1;
    }

    const int lane = tid & 31, warp = tid >> 5;
    const int mtile = warp >> 1, half = warp & 1;
    const int gid = lane >> 2, tig = lane & 3;

    unsigned* swh = sw + (half * 2 + 0) * 128 * PB;
    unsigned* swl = sw + (half * 2 + 1) * 128 * PB;

    float acc[16][4];
#pragma unroll
    for (int j = 0; j < 16; j++)
#pragma unroll
        for (int q = 0; q < 4; q++) acc[j][q] = 0.f;

    const __nv_bfloat16* wbhS = g_wbh[mS];
    const __nv_bfloat16* wblS = g_wbl[mS];
    const __nv_bfloat16* wbhD = g_wbh[mD];
    const __nv_bfloat16* wblD = g_wbl[mD];

    for (int ch = 0; ch < 4; ch++) {
        __syncthreads();
        {
            int n = tid >> 2, q = tid & 3;
            int gsrc = (n * FD + ch * 32) / 8 + q;
            int wdst = n * PB + q * 4;
            ((uint4*)(sw + 0 * 128 * PB + wdst))[0] = ((const uint4*)wbhS)[gsrc];
            ((uint4*)(sw + 1 * 128 * PB + wdst))[0] = ((const uint4*)wblS)[gsrc];
            ((uint4*)(sw + 2 * 128 * PB + wdst))[0] = ((const uint4*)wbhD)[gsrc];
            ((uint4*)(sw + 3 * 128 * PB + wdst))[0] = ((const uint4*)wblD)[gsrc];
        }
        __syncthreads();

#pragma unroll
        for (int kk = 0; kk < 2; kk++) {
            int kb = ch * 16 + kk * 8;
            int row0 = mtile * 16 + gid;
            unsigned A0[4], A1[4];
            A0[0] = sf0[ row0      * PA + kb + tig];
            A0[1] = sf0[(row0 + 8) * PA + kb + tig];
            A0[2] = sf0[ row0      * PA + kb + tig + 4];
            A0[3] = sf0[(row0 + 8) * PA + kb + tig + 4];
            A1[0] = sf1[ row0      * PA + kb + tig];
            A1[1] = sf1[(row0 + 8) * PA + kb + tig];
            A1[2] = sf1[ row0      * PA + kb + tig + 4];
            A1[3] = sf1[(row0 + 8) * PA + kb + tig + 4];
            int kl = kk * 8 + tig;
#pragma unroll
            for (int j = 0; j < 16; j++) {
                int n = j * 8 + gid;
                unsigned b0h = swh[n * PB + kl], b1h = swh[n * PB + kl + 4];
                unsigned b0l = swl[n * PB + kl], b1l = swl[n * PB + kl + 4];
                MMA_BF16(acc[j], A0, b0h, b1h);
                MMA_BF16(acc[j], A0, b0l, b1l);
                MMA_BF16(acc[j], A1, b0h, b1h);
            }
        }
    }

    int r0 = rowbase + mtile * 16 + gid;
    int r1 = r0 + 8;
    if (half == 0) {
        // el -> fp16 buffer
        __half* outh = (LAYER == 1) ? g_el1h : g_el2h;
        const float* bias = bs;
#pragma unroll
        for (int j = 0; j < 16; j++) {
            int col = j * 8 + tig * 2;
            float b0 = __ldg(bias + col), b1 = __ldg(bias + col + 1);
            if (r0 < nrows)
                *(__half2*)(outh + (size_t)r0 * FD + col) =
                    __floats2half2_rn(acc[j][0] + b0, acc[j][1] + b1);
            if (r1 < nrows)
                *(__half2*)(outh + (size_t)r1 * FD + col) =
                    __floats2half2_rn(acc[j][2] + b0, acc[j][3] + b1);
        }
    } else {
        // er -> fp32 buffer
        float* out = (LAYER == 1) ? g_er1 : g_er2;
        const float* bias = bd;
#pragma unroll
        for (int j = 0; j < 16; j++) {
            int col = j * 8 + tig * 2;
            float b0 = __ldg(bias + col), b1 = __ldg(bias + col + 1);
            if (r0 < nrows)
                *(float2*)(out + (size_t)r0 * FD + col) =
                    make_float2(acc[j][0] + b0, acc[j][1] + b1);
            if (r1 < nrows)
                *(float2*)(out + (size_t)r1 * FD + col) =
                    make_float2(acc[j][2] + b0, acc[j][3] + b1);
        }
    }
}

// ---------------- fused per-node GATv2 aggregation (4-edge unroll, fp16 el) --------
template<int LAYER>
__global__ void __launch_bounds__(256)
k_node(const float* __restrict__ attn, float* __restrict__ out,
       const int* __restrict__ nid, int N)
{
    const __half* el  = (LAYER == 1) ? g_el1h : g_el2h;
    const float*  er  = (LAYER == 1) ? g_er1  : g_er2;
    const int*    off = (LAYER == 1) ? g_off1 : g_off2;
    const int*    csr = (LAYER == 1) ? g_csr1 : g_csr2;

    int v    = (blockIdx.x * blockDim.x + threadIdx.x) >> 5;
    int lane = threadIdx.x & 31;
    if (v >= N) return;

    int i0 = __ldg(off + v), i1 = __ldg(off + v + 1);
    float4 t = ((const float4*)attn)[lane];
    float4 r = ((const float4*)(er + (size_t)v * FD))[lane];

    float4 acc = make_float4(0.f, 0.f, 0.f, 0.f);
    float den = 0.f;

    int i = i0;
    for (; i + 4 <= i1; i += 4) {
        int u0 = __ldg(csr + i),     u1 = __ldg(csr + i + 1);
        int u2 = __ldg(csr + i + 2), u3 = __ldg(csr + i + 3);
        float4 a0 = ldh8_na(el + (size_t)u0 * FD, lane);
        float4 a1 = ldh8_na(el + (size_t)u1 * FD, lane);
        float4 a2 = ldh8_na(el + (size_t)u2 * FD, lane);
        float4 a3 = ldh8_na(el + (size_t)u3 * FD, lane);
        float p0 = lrelu(a0.x + r.x, 0.2f) * t.x + lrelu(a0.y + r.y, 0.2f) * t.y
                 + lrelu(a0.z + r.z, 0.2f) * t.z + lrelu(a0.w + r.w, 0.2f) * t.w;
        float p1 = lrelu(a1.x + r.x, 0.2f) * t.x + lrelu(a1.y + r.y, 0.2f) * t.y
                 + lrelu(a1.z + r.z, 0.2f) * t.z + lrelu(a1.w + r.w, 0.2f) * t.w;
        float p2 = lrelu(a2.x + r.x, 0.2f) * t.x + lrelu(a2.y + r.y, 0.2f) * t.y
                 + lrelu(a2.z + r.z, 0.2f) * t.z + lrelu(a2.w + r.w, 0.2f) * t.w;
        float p3 = lrelu(a3.x + r.x, 0.2f) * t.x + lrelu(a3.y + r.y, 0.2f) * t.y
                 + lrelu(a3.z + r.z, 0.2f) * t.z + lrelu(a3.w + r.w, 0.2f) * t.w;
#pragma unroll
        for (int o = 16; o; o >>= 1) {
            p0 += __shfl_xor_sync(0xffffffffu, p0, o);
            p1 += __shfl_xor_sync(0xffffffffu, p1, o);
            p2 += __shfl_xor_sync(0xffffffffu, p2, o);
            p3 += __shfl_xor_sync(0xffffffffu, p3, o);
        }
        float e0 = __expf(p0), e1 = __expf(p1), e2 = __expf(p2), e3 = __expf(p3);
        den += (e0 + e1) + (e2 + e3);
        acc.x += e0 * a0.x + e1 * a1.x + e2 * a2.x + e3 * a3.x;
        acc.y += e0 * a0.y + e1 * a1.y + e2 * a2.y + e3 * a3.y;
        acc.z += e0 * a0.z + e1 * a1.z + e2 * a2.z + e3 * a3.z;
        acc.w += e0 * a0.w + e1 * a1.w + e2 * a2.w + e3 * a3.w;
    }
    for (; i < i1; i++) {
        int u0 = __ldg(csr + i);
        float4 a0 = ldh8_na(el + (size_t)u0 * FD, lane);
        float p0 = lrelu(a0.x + r.x, 0.2f) * t.x + lrelu(a0.y + r.y, 0.2f) * t.y
                 + lrelu(a0.z + r.z, 0.2f) * t.z + lrelu(a0.w + r.w, 0.2f) * t.w;
#pragma unroll
        for (int o = 16; o; o >>= 1) p0 += __shfl_xor_sync(0xffffffffu, p0, o);
        float e0 = __expf(p0);
        den += e0;
        acc.x += e0 * a0.x; acc.y += e0 * a0.y;
        acc.z += e0 * a0.z; acc.w += e0 * a0.w;
    }

    float inv = (i1 > i0) ? (1.f / den) : 0.f;
    acc.x = lrelu(acc.x * inv, 0.01f);
    acc.y = lrelu(acc.y * inv, 0.01f);
    acc.z = lrelu(acc.z * inv, 0.01f);
    acc.w = lrelu(acc.w * inv, 0.01f);

    if (LAYER == 2) {
        ((float4*)(out + (size_t)v * FD))[lane] = acc;
    } else {
        ((float4*)(g_h1 + (size_t)v * FD))[lane] = acc;
        float sum = acc.x + acc.y + acc.z + acc.w;
#pragma unroll
        for (int o = 16; o; o >>= 1) sum += __shfl_xor_sync(0xffffffffu, sum, o);
        if (lane == 0 && sum != 0.f) g_map[__ldg(nid + v)] = v;
    }
}

// ---------------- launch ------------------------------------------------------------
extern "C" void kernel_launch(void* const* d_in, const int* in_sizes, int n_in,
                              void* d_out, int out_size)
{
    const float* emb     = (const float*)d_in[0];
    const int*   i2u_src = (const int*)d_in[1];
    const int*   i2u_dst = (const int*)d_in[2];
    const int*   i2u_nid = (const int*)d_in[3];
    const int*   soc_src = (const int*)d_in[4];
    const int*   soc_dst = (const int*)d_in[5];
    const float* Ws1 = (const float*)d_in[6];
    const float* bs1 = (const float*)d_in[7];
    const float* Wd1 = (const float*)d_in[8];
    const float* bd1 = (const float*)d_in[9];
    const float* at1 = (const float*)d_in[10];
    const float* Ws2 = (const float*)d_in[11];
    const float* bs2 = (const float*)d_in[12];
    const float* Wd2 = (const float*)d_in[13];
    const float* bd2 = (const float*)d_in[14];
    const float* at2 = (const float*)d_in[15];
    float* out = (float*)d_out;

    const int E1 = in_sizes[1];
    const int E2 = in_sizes[4];
    const int N1 = in_sizes[3];
    const int NS = out_size / FD;

    int *cnt1, *cnt2, *off1, *off2, *csr1, *csr2, *cs1, *cs2;
    cudaGetSymbolAddress((void**)&cnt1, g_cnt1);
    cudaGetSymbolAddress((void**)&cnt2, g_cnt2);
    cudaGetSymbolAddress((void**)&off1, g_off1);
    cudaGetSymbolAddress((void**)&off2, g_off2);
    cudaGetSymbolAddress((void**)&csr1, g_csr1);
    cudaGetSymbolAddress((void**)&csr2, g_csr2);
    cudaGetSymbolAddress((void**)&cs1,  g_csum1);
    cudaGetSymbolAddress((void**)&cs2,  g_csum2);

    static cudaStream_t s1 = nullptr, s2 = nullptr;
    static cudaEvent_t ev0 = nullptr, ev1 = nullptr, ev2 = nullptr;
    if (!s1) {
        cudaStreamCreateWithFlags(&s1, cudaStreamNonBlocking);
        cudaStreamCreateWithFlags(&s2, cudaStreamNonBlocking);
        cudaEventCreateWithFlags(&ev0, cudaEventDisableTiming);
        cudaEventCreateWithFlags(&ev1, cudaEventDisableTiming);
        cudaEventCreateWithFlags(&ev2, cudaEventDisableTiming);
        cudaFuncSetAttribute(k_gemm_mma<1>, cudaFuncAttributeMaxDynamicSharedMemorySize, GEMM_SMEM);
        cudaFuncSetAttribute(k_gemm_mma<2>, cudaFuncAttributeMaxDynamicSharedMemorySize, GEMM_SMEM);
    }

    const int ch1 = (N1 + 1023) / 1024;
    const int ch2 = (NS + 1023) / 1024;

    // fork side branches off the (captured) main stream
    cudaEventRecord(ev0, 0);
    cudaStreamWaitEvent(s1, ev0, 0);
    cudaStreamWaitEvent(s2, ev0, 0);

    // branch s1: graph-1 CSR + map init
    k_init1<<<(cNSOC + 255) / 256, 256, 0, s1>>>();
    k_hist<<<(E1 + 255) / 256, 256, 0, s1>>>(i2u_dst, cnt1, E1);
    k_scanA<<<ch1, 1024, 0, s1>>>(cnt1, off1, cs1, N1);
    k_scanB<<<1, 128, 0, s1>>>(cs1, ch1);
    k_scanC<<<(N1 + 255) / 256, 256, 0, s1>>>(off1, cs1, cnt1, N1);
    k_scatter<<<(E1 + 255) / 256, 256, 0, s1>>>(i2u_src, i2u_dst, cnt1, csr1, E1);
    cudaEventRecord(ev1, s1);

    // branch s2: graph-2 CSR
    k_init2<<<(cNSOC + 255) / 256, 256, 0, s2>>>();
    k_hist<<<(E2 + 255) / 256, 256, 0, s2>>>(soc_dst, cnt2, E2);
    k_scanA<<<ch2, 1024, 0, s2>>>(cnt2, off2, cs2, NS);
    k_scanB<<<1, 128, 0, s2>>>(cs2, ch2);
    k_scanC<<<(NS + 255) / 256, 256, 0, s2>>>(off2, cs2, cnt2, NS);
    k_scatter<<<(E2 + 255) / 256, 256, 0, s2>>>(soc_src, soc_dst, cnt2, csr2, E2);
    cudaEventRecord(ev2, s2);

    // main: W split, layer-1 GEMM
    k_wsplit<<<256, 256>>>(Ws1, Wd1, Ws2, Wd2);
    k_gemm_mma<1><<<(N1 + 127) / 128, 512, GEMM_SMEM>>>(emb, i2u_nid, bs1, bd1, N1);

    // join graph-1 CSR, aggregate layer 1
    cudaStreamWaitEvent(0, ev1, 0);
    k_node<1><<<(N1 + 7) / 8, 256>>>(at1, nullptr, i2u_nid, N1);

    // layer-2 GEMM (features = map>=0 ? h1 : emb)
    k_gemm_mma<2><<<(NS + 127) / 128, 512, GEMM_SMEM>>>(emb, nullptr, bs2, bd2, NS);

    // join graph-2 CSR, aggregate layer 2 into d_out
    cudaStreamWaitEvent(0, ev2, 0);
    k_node<2><<<(NS + 7) / 8, 256>>>(at2, out, nullptr, NS);
}